// round 12
// baseline (speedup 1.0000x reference)
#include <cuda_runtime.h>
#include <cuda_fp16.h>
#include <cstdint>

#define Nn 8192
#define KIN 512
#define Ff 256
#define ALPHA 0.2f

#define BM 64
#define KC 128
#define NT (Nn / KC)      // 64
#define PSTR 72           // u32 row stride (72 mod 32 = 8 -> conflict-free LDS)

// ---------------- scratch ----------------
__device__ float g_h[Nn * Ff];
__device__ uint32_t g_ht[Ff * Nn / 2];  // h^T fp16 pairs, pair-permuted in 8-pair groups
__device__ float g_sself[Nn];
__device__ float g_e1[Nn];
__device__ float g_e2[Nn];
__device__ float g_sneigh[Nn];
__device__ unsigned g_smax_bits;

// ---------------- helpers ----------------
__device__ __forceinline__ void mma_f16(float* d, uint32_t a0, uint32_t a1,
                                        uint32_t a2, uint32_t a3,
                                        uint32_t b0, uint32_t b1) {
    asm volatile(
        "mma.sync.aligned.m16n8k16.row.col.f32.f16.f16.f32 "
        "{%0,%1,%2,%3}, {%4,%5,%6,%7}, {%8,%9}, {%0,%1,%2,%3};"
        : "+f"(d[0]), "+f"(d[1]), "+f"(d[2]), "+f"(d[3])
        : "r"(a0), "r"(a1), "r"(a2), "r"(a3), "r"(b0), "r"(b1));
}
__device__ __forceinline__ unsigned fkey(float f) {
    unsigned b = __float_as_uint(f);
    return (b & 0x80000000u) ? ~b : (b | 0x80000000u);
}
__device__ __forceinline__ float funkey(unsigned k) {
    unsigned b = (k & 0x80000000u) ? (k & 0x7fffffffu) : ~k;
    return __uint_as_float(b);
}
__device__ __forceinline__ uint32_t smem_u32(const void* p) {
    uint32_t a;
    asm("{ .reg .u64 t; cvta.to.shared.u64 t, %1; cvt.u32.u64 %0, t; }"
        : "=r"(a) : "l"(p));
    return a;
}
__device__ __forceinline__ void cp16(uint32_t dst, const void* src) {
    asm volatile("cp.async.cg.shared.global [%0], [%1], 16;"
                 :: "r"(dst), "l"(src));
}

// ================= kernel 1: h = X @ W =================
__global__ __launch_bounds__(256, 1) void gemm_h_kernel(
    const float* __restrict__ A, const float* __restrict__ B) {
    __shared__ float As[32][65];
    __shared__ float Bs[32][64];
    int tid = threadIdx.x;
    if (blockIdx.x == 0 && blockIdx.y == 0 && tid == 0) g_smax_bits = 0u;
    int tx = tid & 15, ty = tid >> 4;
    int m0 = blockIdx.y * 64, n0 = blockIdx.x * 64;
    float acc[4][4];
#pragma unroll
    for (int i = 0; i < 4; i++)
#pragma unroll
        for (int j = 0; j < 4; j++) acc[i][j] = 0.f;
    for (int k0 = 0; k0 < KIN; k0 += 32) {
#pragma unroll
        for (int v = 0; v < 8; v++) {
            int idx = v * 256 + tid;
            int m = idx >> 5, k = idx & 31;
            As[k][m] = A[(size_t)(m0 + m) * KIN + k0 + k];
        }
#pragma unroll
        for (int v = 0; v < 8; v++) {
            int idx = v * 256 + tid;
            int k = idx >> 6, n = idx & 63;
            Bs[k][n] = B[(size_t)(k0 + k) * Ff + n0 + n];
        }
        __syncthreads();
#pragma unroll
        for (int k = 0; k < 32; k++) {
            float a0[4], b0[4];
#pragma unroll
            for (int i = 0; i < 4; i++) a0[i] = As[k][ty * 4 + i];
            float4 bv = *(const float4*)&Bs[k][tx * 4];
            b0[0] = bv.x; b0[1] = bv.y; b0[2] = bv.z; b0[3] = bv.w;
#pragma unroll
            for (int i = 0; i < 4; i++)
#pragma unroll
                for (int j = 0; j < 4; j++) acc[i][j] += a0[i] * b0[j];
        }
        __syncthreads();
    }
#pragma unroll
    for (int i = 0; i < 4; i++) {
        float4 o = make_float4(acc[i][0], acc[i][1], acc[i][2], acc[i][3]);
        *(float4*)&g_h[(size_t)(m0 + ty * 4 + i) * Ff + n0 + tx * 4] = o;
    }
}

// ================= kernel 1b: transpose + fp16 convert (pair-permuted) =================
__global__ __launch_bounds__(256) void transpose_f16_kernel() {
    __shared__ float ts[64][65];
    int m0 = blockIdx.x * 64;   // j
    int n0 = blockIdx.y * 64;   // f
    int tid = threadIdx.x;
    int c = tid & 63, r = tid >> 6;
#pragma unroll
    for (int rr = 0; rr < 16; rr++)
        ts[r + rr * 4][c] = g_h[(size_t)(m0 + r + rr * 4) * Ff + n0 + c];
    __syncthreads();
    int nl = tid >> 2;          // f local
    int mb = (tid & 3) * 16;    // 16 j = one 8-pair group
    uint32_t* dst = g_ht + (size_t)(n0 + nl) * (Nn / 2) + (m0 >> 1);
#pragma unroll
    for (int q = 0; q < 8; q++) {
        __half2 h = __floats2half2_rn(ts[mb + 2 * q][nl], ts[mb + 2 * q + 1][nl]);
        int slot = 2 * (q & 3) + (q >> 2);
        dst[(mb >> 1) + slot] = *(uint32_t*)&h;
    }
}

// ================= kernel 2: s_self / s_neigh + e1,e2 + global max =================
__global__ __launch_bounds__(256) void attn_vec_kernel(const float* __restrict__ a) {
    int i = blockIdx.x;
    int t = threadIdx.x;
    float v = g_h[(size_t)i * Ff + t];
    float p1 = v * a[t];
    float p2 = v * a[Ff + t];
#pragma unroll
    for (int o = 16; o; o >>= 1) {
        p1 += __shfl_down_sync(0xffffffffu, p1, o);
        p2 += __shfl_down_sync(0xffffffffu, p2, o);
    }
    __shared__ float s1[8], s2[8];
    if ((t & 31) == 0) { s1[t >> 5] = p1; s2[t >> 5] = p2; }
    __syncthreads();
    if (t == 0) {
        float a1 = 0.f, a2 = 0.f;
#pragma unroll
        for (int w = 0; w < 8; w++) { a1 += s1[w]; a2 += s2[w]; }
        g_sself[i] = a1;
        g_sneigh[i] = a2;
        g_e1[i] = __expf(a2);
        g_e2[i] = __expf(ALPHA * a2);
        atomicMax(&g_smax_bits, fkey(a2));
    }
}

// ================= kernel 3: fp16 HMMA masked softmax-GEMM =================
// KC=128, genP interleaved into the kk loop. 512 threads.
#define SMEM_MAIN ((2 * 256 * PSTR + 2 * BM * PSTR) * 4 + BM * 4)
__global__ __launch_bounds__(512, 1) void attn_main_kernel(
    const int* __restrict__ adj, float* __restrict__ out) {
    extern __shared__ char smem[];
    uint32_t* bs = (uint32_t*)smem;                  // [2][256][PSTR]
    uint32_t* ps = bs + 2 * 256 * PSTR;              // [2][BM][PSTR]
    float* zs = (float*)(ps + 2 * BM * PSTR);        // [BM]

    int tid = threadIdx.x, w = tid >> 5, lane = tid & 31;
    int g = lane >> 2, t4 = lane & 3;
    int r0 = blockIdx.x * BM;

    // ---- per-thread row constants (4 rows per warp) ----
    float c1r[4], c2r[4], thrr[4];
    float smax = funkey(g_smax_bits);
#pragma unroll
    for (int ri = 0; ri < 4; ri++) {
        float ss = g_sself[r0 + w * 4 + ri];
        float x = ss + smax;
        float m = (x >= 0.f) ? x : ALPHA * x;
        c1r[ri] = __expf(ss - m);
        c2r[ri] = __expf(ALPHA * ss - m);
        thrr[ri] = -ss;
    }

    // P-gen: thread owns j-quad j0 = 4*lane (pairs 2*lane, 2*lane+1)
    int j0 = 4 * lane;
    int p0i = 2 * lane, p1i = 2 * lane + 1;
    int pcol0 = (p0i & ~7) + 2 * (p0i & 3) + ((p0i >> 2) & 1);
    int pcol1 = (p1i & ~7) + 2 * (p1i & 3) + ((p1i >> 2) & 1);

    // cp.async B: thread owns f-row tid>>1, half (tid&1)*32 u32 (chunk row = 64 u32)
    int brow = tid >> 1, bq = (tid & 1) * 32;
    const uint32_t* srcB = g_ht + (size_t)brow * (Nn / 2) + bq;
    uint32_t sb = smem_u32(smem);
    uint32_t dstB[2] = {sb + (uint32_t)(brow * PSTR + bq) * 4,
                        sb + (uint32_t)(256 * PSTR + brow * PSTR + bq) * 4};

    // ---- prologue: issue B0 and B1 ----
#pragma unroll
    for (int b = 0; b < 8; b++) cp16(dstB[0] + b * 16, srcB + b * 4);
    asm volatile("cp.async.commit_group;");
#pragma unroll
    for (int b = 0; b < 8; b++) cp16(dstB[1] + b * 16, srcB + (KC / 2) + b * 4);
    asm volatile("cp.async.commit_group;");

    // ---- state chunk 0 ----
    const int* abase = adj + (size_t)(r0 + w * 4) * Nn;
    int4 av[4];
    float4 e1v, e2v, snv;
#pragma unroll
    for (int ri = 0; ri < 4; ri++) av[ri] = *(const int4*)(abase + (size_t)ri * Nn + j0);
    e1v = *(const float4*)&g_e1[j0];
    e2v = *(const float4*)&g_e2[j0];
    snv = *(const float4*)&g_sneigh[j0];

    float zpart[4];
#pragma unroll
    for (int ri = 0; ri < 4; ri++) zpart[ri] = 0.f;

    // genP(0) all 4 rows
    {
        uint32_t* pw = ps + (w * 4) * PSTR;
#pragma unroll
        for (int ri = 0; ri < 4; ri++) {
            int4 a = av[ri];
            float p0 = (snv.x >= thrr[ri]) ? c1r[ri] * e1v.x : c2r[ri] * e2v.x;
            p0 = (a.x > 0) ? p0 : 0.f;
            float p1 = (snv.y >= thrr[ri]) ? c1r[ri] * e1v.y : c2r[ri] * e2v.y;
            p1 = (a.y > 0) ? p1 : 0.f;
            float p2 = (snv.z >= thrr[ri]) ? c1r[ri] * e1v.z : c2r[ri] * e2v.z;
            p2 = (a.z > 0) ? p2 : 0.f;
            float p3 = (snv.w >= thrr[ri]) ? c1r[ri] * e1v.w : c2r[ri] * e2v.w;
            p3 = (a.w > 0) ? p3 : 0.f;
            zpart[ri] += (p0 + p1) + (p2 + p3);
            __half2 h01 = __floats2half2_rn(p0, p1);
            __half2 h23 = __floats2half2_rn(p2, p3);
            pw[ri * PSTR + pcol0] = *(uint32_t*)&h01;
            pw[ri * PSTR + pcol1] = *(uint32_t*)&h23;
        }
    }

    // state chunk 1
#pragma unroll
    for (int ri = 0; ri < 4; ri++)
        av[ri] = *(const int4*)(abase + (size_t)ri * Nn + KC + j0);
    e1v = *(const float4*)&g_e1[KC + j0];
    e2v = *(const float4*)&g_e2[KC + j0];
    snv = *(const float4*)&g_sneigh[KC + j0];

    asm volatile("cp.async.wait_group 1;");   // B0 resident
    __syncthreads();

    int wm = w & 1, wn = w >> 1;
    float acc[2][4][4];
#pragma unroll
    for (int mt = 0; mt < 2; mt++)
#pragma unroll
        for (int s = 0; s < 4; s++)
#pragma unroll
            for (int q = 0; q < 4; q++) acc[mt][s][q] = 0.f;

    for (int tch = 0; tch < NT; tch++) {
        int buf = tch & 1;
        uint32_t* pwn = ps + (buf ^ 1) * BM * PSTR + (w * 4) * PSTR;
        const uint32_t* bt = bs + buf * 256 * PSTR + (wn * 32 + g) * PSTR + 2 * t4;
        const uint32_t* pa = ps + buf * BM * PSTR + (wm * 32) * PSTR + 2 * t4;
        bool genp = (tch + 1 < NT);

        // ---- 8 k-steps; genP rows interleaved at kk=0..3 ----
#pragma unroll
        for (int kk = 0; kk < 8; kk++) {
            int co = kk * 8;
            uint2 ra0 = *(const uint2*)(pa + (g) * PSTR + co);
            uint2 ra1 = *(const uint2*)(pa + (g + 8) * PSTR + co);
            uint2 ra2 = *(const uint2*)(pa + (16 + g) * PSTR + co);
            uint2 ra3 = *(const uint2*)(pa + (16 + g + 8) * PSTR + co);
#pragma unroll
            for (int s = 0; s < 4; s++) {
                uint2 b = *(const uint2*)(bt + (s * 8) * PSTR + co);
                mma_f16(acc[0][s], ra0.x, ra1.x, ra0.y, ra1.y, b.x, b.y);
                mma_f16(acc[1][s], ra2.x, ra3.x, ra2.y, ra3.y, b.x, b.y);
            }
            if (kk < 4 && genp) {
                int ri = kk;
                int4 a = av[ri];
                float p0 = (snv.x >= thrr[ri]) ? c1r[ri] * e1v.x : c2r[ri] * e2v.x;
                p0 = (a.x > 0) ? p0 : 0.f;
                float p1 = (snv.y >= thrr[ri]) ? c1r[ri] * e1v.y : c2r[ri] * e2v.y;
                p1 = (a.y > 0) ? p1 : 0.f;
                float p2 = (snv.z >= thrr[ri]) ? c1r[ri] * e1v.z : c2r[ri] * e2v.z;
                p2 = (a.z > 0) ? p2 : 0.f;
                float p3 = (snv.w >= thrr[ri]) ? c1r[ri] * e1v.w : c2r[ri] * e2v.w;
                p3 = (a.w > 0) ? p3 : 0.f;
                zpart[ri] += (p0 + p1) + (p2 + p3);
                __half2 h01 = __floats2half2_rn(p0, p1);
                __half2 h23 = __floats2half2_rn(p2, p3);
                pwn[ri * PSTR + pcol0] = *(uint32_t*)&h01;
                pwn[ri * PSTR + pcol1] = *(uint32_t*)&h23;
            }
        }

        // ---- prefetch state(t+2) ----
        if (tch + 2 < NT) {
            int jn = (tch + 2) * KC + j0;
#pragma unroll
            for (int ri = 0; ri < 4; ri++)
                av[ri] = *(const int4*)(abase + (size_t)ri * Nn + jn);
            e1v = *(const float4*)&g_e1[jn];
            e2v = *(const float4*)&g_e2[jn];
            snv = *(const float4*)&g_sneigh[jn];
        }

        asm volatile("cp.async.wait_group 0;");   // B(t+1) resident
        __syncthreads();                          // ps[buf^1] + bs[buf] free

        // ---- issue B(t+2) into bs[buf] ----
        if (tch + 2 < NT) {
            const uint32_t* s = srcB + (size_t)(tch + 2) * (KC / 2);
#pragma unroll
            for (int b = 0; b < 8; b++) cp16(dstB[buf] + b * 16, s + b * 4);
        }
        asm volatile("cp.async.commit_group;");
    }

    // ---- Z reduce ----
#pragma unroll
    for (int ri = 0; ri < 4; ri++) {
        float z = zpart[ri];
#pragma unroll
        for (int o = 16; o; o >>= 1) z += __shfl_xor_sync(0xffffffffu, z, o);
        if (lane == 0) zs[w * 4 + ri] = z;
    }
    __syncthreads();

    // ---- epilogue ----
#pragma unroll
    for (int mt = 0; mt < 2; mt++) {
#pragma unroll
        for (int half = 0; half < 2; half++) {
            int rl = wm * 32 + mt * 16 + g + half * 8;
            float invz = 1.0f / zs[rl];
            float* orow = out + (size_t)(r0 + rl) * Ff + wn * 32 + 2 * t4;
#pragma unroll
            for (int s = 0; s < 4; s++) {
                float v0 = acc[mt][s][2 * half] * invz;
                float v1 = acc[mt][s][2 * half + 1] * invz;
                float2 o;
                o.x = (v0 > 0.f) ? v0 : expm1f(v0);
                o.y = (v1 > 0.f) ? v1 : expm1f(v1);
                *(float2*)(orow + s * 8) = o;
            }
        }
    }
}

// ================= launcher =================
extern "C" void kernel_launch(void* const* d_in, const int* in_sizes, int n_in,
                              void* d_out, int out_size) {
    const float* input = (const float*)d_in[0];
    const int*   adj   = (const int*)d_in[1];
    const float* W     = (const float*)d_in[2];
    const float* a     = (const float*)d_in[3];
    float* out = (float*)d_out;

    static int smem_set = 0;
    if (!smem_set) {
        cudaFuncSetAttribute(attn_main_kernel,
                             cudaFuncAttributeMaxDynamicSharedMemorySize, SMEM_MAIN);
        smem_set = 1;
    }

    dim3 g1(Ff / 64, Nn / 64);
    gemm_h_kernel<<<g1, 256>>>(input, W);
    dim3 g2(Nn / 64, Ff / 64);
    transpose_f16_kernel<<<g2, 256>>>();
    attn_vec_kernel<<<Nn, 256>>>(a);
    attn_main_kernel<<<Nn / BM, 512, SMEM_MAIN>>>(adj, out);
}

// round 13
// speedup vs baseline: 1.0763x; 1.0763x over previous
#include <cuda_runtime.h>
#include <cuda_fp16.h>
#include <cstdint>

#define Nn 8192
#define KIN 512
#define Ff 256
#define ALPHA 0.2f

#define BM 64
#define KC 64
#define NT (Nn / KC)      // 128
#define PSTR 40           // u32 row stride for P and B smem tiles (conflict-free)

// ---------------- scratch ----------------
__device__ float g_h[Nn * Ff];
__device__ uint32_t g_ht[Ff * Nn / 2];  // h^T fp16 pairs, pair-permuted in 8-pair groups
__device__ float g_sself[Nn];
__device__ float g_e1[Nn];
__device__ float g_e2[Nn];
__device__ float g_sneigh[Nn];
__device__ unsigned g_smax_bits;

// ---------------- helpers ----------------
__device__ __forceinline__ void mma_f16(float* d, uint32_t a0, uint32_t a1,
                                        uint32_t a2, uint32_t a3,
                                        uint32_t b0, uint32_t b1) {
    asm volatile(
        "mma.sync.aligned.m16n8k16.row.col.f32.f16.f16.f32 "
        "{%0,%1,%2,%3}, {%4,%5,%6,%7}, {%8,%9}, {%0,%1,%2,%3};"
        : "+f"(d[0]), "+f"(d[1]), "+f"(d[2]), "+f"(d[3])
        : "r"(a0), "r"(a1), "r"(a2), "r"(a3), "r"(b0), "r"(b1));
}
__device__ __forceinline__ unsigned fkey(float f) {
    unsigned b = __float_as_uint(f);
    return (b & 0x80000000u) ? ~b : (b | 0x80000000u);
}
__device__ __forceinline__ float funkey(unsigned k) {
    unsigned b = (k & 0x80000000u) ? (k & 0x7fffffffu) : ~k;
    return __uint_as_float(b);
}
__device__ __forceinline__ uint32_t smem_u32(const void* p) {
    uint32_t a;
    asm("{ .reg .u64 t; cvta.to.shared.u64 t, %1; cvt.u32.u64 %0, t; }"
        : "=r"(a) : "l"(p));
    return a;
}
__device__ __forceinline__ void cp16(uint32_t dst, const void* src) {
    asm volatile("cp.async.cg.shared.global [%0], [%1], 16;"
                 :: "r"(dst), "l"(src));
}
__device__ __forceinline__ int pairperm(int p) {   // perm within 8-pair groups
    return (p & ~7) + 2 * (p & 3) + ((p & 7) >> 2);
}

// ================= kernel 1: h = X @ W  (+ fused transposed fp16 store) =================
__global__ __launch_bounds__(256, 1) void gemm_h_kernel(
    const float* __restrict__ A, const float* __restrict__ B) {
    __shared__ float As[32][65];
    __shared__ float Bs[32][64];
    int tid = threadIdx.x;
    if (blockIdx.x == 0 && blockIdx.y == 0 && tid == 0) g_smax_bits = 0u;
    int tx = tid & 15, ty = tid >> 4;
    int m0 = blockIdx.y * 64, n0 = blockIdx.x * 64;
    float acc[4][4];
#pragma unroll
    for (int i = 0; i < 4; i++)
#pragma unroll
        for (int j = 0; j < 4; j++) acc[i][j] = 0.f;
    for (int k0 = 0; k0 < KIN; k0 += 32) {
#pragma unroll
        for (int v = 0; v < 8; v++) {
            int idx = v * 256 + tid;
            int m = idx >> 5, k = idx & 31;
            As[k][m] = A[(size_t)(m0 + m) * KIN + k0 + k];
        }
#pragma unroll
        for (int v = 0; v < 8; v++) {
            int idx = v * 256 + tid;
            int k = idx >> 6, n = idx & 63;
            Bs[k][n] = B[(size_t)(k0 + k) * Ff + n0 + n];
        }
        __syncthreads();
#pragma unroll
        for (int k = 0; k < 32; k++) {
            float a0[4], b0[4];
#pragma unroll
            for (int i = 0; i < 4; i++) a0[i] = As[k][ty * 4 + i];
            float4 bv = *(const float4*)&Bs[k][tx * 4];
            b0[0] = bv.x; b0[1] = bv.y; b0[2] = bv.z; b0[3] = bv.w;
#pragma unroll
            for (int i = 0; i < 4; i++)
#pragma unroll
                for (int j = 0; j < 4; j++) acc[i][j] += a0[i] * b0[j];
        }
        __syncthreads();
    }
#pragma unroll
    for (int i = 0; i < 4; i++) {
        float4 o = make_float4(acc[i][0], acc[i][1], acc[i][2], acc[i][3]);
        *(float4*)&g_h[(size_t)(m0 + ty * 4 + i) * Ff + n0 + tx * 4] = o;
    }
    // fused transposed fp16 store: rows m are j's, cols are features
    int pbase = (m0 + ty * 4) >> 1;          // global pair index (2 pairs per thread)
    int d0 = pairperm(pbase), d1 = pairperm(pbase + 1);
#pragma unroll
    for (int j = 0; j < 4; j++) {
        int f = n0 + tx * 4 + j;
        __half2 h01 = __floats2half2_rn(acc[0][j], acc[1][j]);
        __half2 h23 = __floats2half2_rn(acc[2][j], acc[3][j]);
        uint32_t* drow = g_ht + (size_t)f * (Nn / 2);
        drow[d0] = *(uint32_t*)&h01;
        drow[d1] = *(uint32_t*)&h23;
    }
}

// ================= kernel 2: s_self / s_neigh + e1,e2 + global max (warp-per-row) =====
__global__ __launch_bounds__(256) void attn_vec_kernel(const float* __restrict__ a) {
    int w = threadIdx.x >> 5, lane = threadIdx.x & 31;
    int i = blockIdx.x * 8 + w;
    const float4* hrow = (const float4*)(g_h + (size_t)i * Ff);
    float p1 = 0.f, p2 = 0.f;
#pragma unroll
    for (int q = 0; q < 2; q++) {
        int e = lane + q * 32;
        float4 v = hrow[e];
        float4 a1 = *(const float4*)(a + 4 * e);
        float4 a2 = *(const float4*)(a + Ff + 4 * e);
        p1 += v.x * a1.x + v.y * a1.y + v.z * a1.z + v.w * a1.w;
        p2 += v.x * a2.x + v.y * a2.y + v.z * a2.z + v.w * a2.w;
    }
#pragma unroll
    for (int o = 16; o; o >>= 1) {
        p1 += __shfl_down_sync(0xffffffffu, p1, o);
        p2 += __shfl_down_sync(0xffffffffu, p2, o);
    }
    if (lane == 0) {
        g_sself[i] = p1;
        g_sneigh[i] = p2;
        g_e1[i] = __expf(p2);
        g_e2[i] = __expf(ALPHA * p2);
        atomicMax(&g_smax_bits, fkey(p2));
    }
}

// ================= kernel 3: fp16 HMMA masked softmax-GEMM (3-stage B ring) ===========
// 512 threads. Warp (wm,wn): rows wm*32+, cols wn*32+. P-gen: warp w rows w*4..w*4+3.
#define SMEM_MAIN ((3 * 256 * PSTR + 2 * BM * PSTR) * 4 + BM * 4)
__global__ __launch_bounds__(512, 1) void attn_main_kernel(
    const int* __restrict__ adj, float* __restrict__ out) {
    extern __shared__ char smem[];
    uint32_t* bs = (uint32_t*)smem;                  // [3][256][PSTR]
    uint32_t* ps = bs + 3 * 256 * PSTR;              // [2][BM][PSTR]
    float* zs = (float*)(ps + 2 * BM * PSTR);        // [BM]

    int tid = threadIdx.x, w = tid >> 5, lane = tid & 31;
    int g = lane >> 2, t4 = lane & 3;
    int r0 = blockIdx.x * BM;

    // ---- per-thread row constants (4 rows per warp) ----
    float c1r[4], c2r[4], thrr[4];
    float smax = funkey(g_smax_bits);
#pragma unroll
    for (int ri = 0; ri < 4; ri++) {
        float ss = g_sself[r0 + w * 4 + ri];
        float x = ss + smax;
        float m = (x >= 0.f) ? x : ALPHA * x;
        c1r[ri] = __expf(ss - m);
        c2r[ri] = __expf(ALPHA * ss - m);
        thrr[ri] = -ss;
    }

    // P-gen: thread owns j-pair = lane (j = 2*lane, 2*lane+1)
    int j0 = 2 * lane;
    int l7 = lane & 7;
    int pcol = ((lane >> 3) << 3) + 2 * (l7 & 3) + (l7 >> 2);

    // cp.async B: thread owns f-row tid>>1, quarter-row (tid&1)*16 u32
    int brow = tid >> 1, bq = (tid & 1) * 16;
    const uint32_t* srcB = g_ht + (size_t)brow * (Nn / 2) + bq;
    uint32_t sb = smem_u32(smem);
    uint32_t dBoff = (uint32_t)(brow * PSTR + bq) * 4;   // offset within a slot
    const uint32_t SLOT = 256 * PSTR * 4;

    // ---- prologue: issue B0 (slot0) and B1 (slot1) ----
#pragma unroll
    for (int b = 0; b < 4; b++) cp16(sb + dBoff + b * 16, srcB + b * 4);
    asm volatile("cp.async.commit_group;");
#pragma unroll
    for (int b = 0; b < 4; b++) cp16(sb + SLOT + dBoff + b * 16, srcB + (KC / 2) + b * 4);
    asm volatile("cp.async.commit_group;");

    // ---- state chunk 0; gen P0 ----
    const int* abase = adj + (size_t)(r0 + w * 4) * Nn;
    int2 av[4];
    float2 e1v, e2v, snv;
#pragma unroll
    for (int ri = 0; ri < 4; ri++) av[ri] = *(const int2*)(abase + (size_t)ri * Nn + j0);
    e1v = *(const float2*)&g_e1[j0];
    e2v = *(const float2*)&g_e2[j0];
    snv = *(const float2*)&g_sneigh[j0];

    float zpart[4];
#pragma unroll
    for (int ri = 0; ri < 4; ri++) zpart[ri] = 0.f;

    {
        uint32_t* pw = ps + (w * 4) * PSTR;
#pragma unroll
        for (int ri = 0; ri < 4; ri++) {
            int2 a = av[ri];
            bool pos0 = snv.x >= thrr[ri];
            float p0 = (pos0 ? c1r[ri] : c2r[ri]) * (pos0 ? e1v.x : e2v.x);
            p0 = (a.x > 0) ? p0 : 0.f;
            bool pos1 = snv.y >= thrr[ri];
            float p1 = (pos1 ? c1r[ri] : c2r[ri]) * (pos1 ? e1v.y : e2v.y);
            p1 = (a.y > 0) ? p1 : 0.f;
            zpart[ri] += p0 + p1;
            __half2 h = __floats2half2_rn(p0, p1);
            pw[ri * PSTR + pcol] = *(uint32_t*)&h;
        }
    }

    // state chunk 1
#pragma unroll
    for (int ri = 0; ri < 4; ri++)
        av[ri] = *(const int2*)(abase + (size_t)ri * Nn + KC + j0);
    e1v = *(const float2*)&g_e1[KC + j0];
    e2v = *(const float2*)&g_e2[KC + j0];
    snv = *(const float2*)&g_sneigh[KC + j0];

    asm volatile("cp.async.wait_group 1;");   // B0 resident
    __syncthreads();

    int wm = w & 1, wn = w >> 1;
    float acc[2][4][4];
#pragma unroll
    for (int mt = 0; mt < 2; mt++)
#pragma unroll
        for (int s = 0; s < 4; s++)
#pragma unroll
            for (int q = 0; q < 4; q++) acc[mt][s][q] = 0.f;

    int scur = 0, snxt = 2;                   // B ring slots: MMA reads scur, write snxt

    for (int tch = 0; tch < NT; tch++) {
        int buf = tch & 1;

        // ---- issue B(t+2) into ring slot snxt (freed by MMA(t-1) before last barrier) ----
        if (tch + 2 < NT) {
            const uint32_t* s = srcB + (size_t)(tch + 2) * (KC / 2);
            uint32_t d = sb + (uint32_t)snxt * SLOT + dBoff;
#pragma unroll
            for (int b = 0; b < 4; b++) cp16(d + b * 16, s + b * 4);
        }
        asm volatile("cp.async.commit_group;");

        // ---- genP(t+1) into ps[buf^1] ----
        if (tch + 1 < NT) {
            uint32_t* pw = ps + (buf ^ 1) * BM * PSTR + (w * 4) * PSTR;
#pragma unroll
            for (int ri = 0; ri < 4; ri++) {
                int2 a = av[ri];
                bool pos0 = snv.x >= thrr[ri];
                float p0 = (pos0 ? c1r[ri] : c2r[ri]) * (pos0 ? e1v.x : e2v.x);
                p0 = (a.x > 0) ? p0 : 0.f;
                bool pos1 = snv.y >= thrr[ri];
                float p1 = (pos1 ? c1r[ri] : c2r[ri]) * (pos1 ? e1v.y : e2v.y);
                p1 = (a.y > 0) ? p1 : 0.f;
                zpart[ri] += p0 + p1;
                __half2 h = __floats2half2_rn(p0, p1);
                pw[ri * PSTR + pcol] = *(uint32_t*)&h;
            }
        }

        // ---- MMA(t): warp tile 32x32, K=64 (4 k-steps of 16), B from slot scur ----
        {
            const uint32_t* bt = bs + scur * 256 * PSTR + (wn * 32 + g) * PSTR + 2 * t4;
            const uint32_t* pa = ps + buf * BM * PSTR + (wm * 32) * PSTR + 2 * t4;
#pragma unroll
            for (int kk = 0; kk < 4; kk++) {
                int co = kk * 8;
                uint2 ra0 = *(const uint2*)(pa + (g) * PSTR + co);
                uint2 ra1 = *(const uint2*)(pa + (g + 8) * PSTR + co);
                uint2 ra2 = *(const uint2*)(pa + (16 + g) * PSTR + co);
                uint2 ra3 = *(const uint2*)(pa + (16 + g + 8) * PSTR + co);
#pragma unroll
                for (int s = 0; s < 4; s++) {
                    uint2 b = *(const uint2*)(bt + (s * 8) * PSTR + co);
                    mma_f16(acc[0][s], ra0.x, ra1.x, ra0.y, ra1.y, b.x, b.y);
                    mma_f16(acc[1][s], ra2.x, ra3.x, ra2.y, ra3.y, b.x, b.y);
                }
            }
        }

        // ---- prefetch state(t+2) ----
        if (tch + 2 < NT) {
            int jn = (tch + 2) * KC + j0;
#pragma unroll
            for (int ri = 0; ri < 4; ri++)
                av[ri] = *(const int2*)(abase + (size_t)ri * Nn + jn);
            e1v = *(const float2*)&g_e1[jn];
            e2v = *(const float2*)&g_e2[jn];
            snv = *(const float2*)&g_sneigh[jn];
        }

        asm volatile("cp.async.wait_group 1;");   // B(t+1) resident; B(t+2) may fly
        __syncthreads();                          // ps[buf^1] published, slot rotation safe

        scur = (scur == 2) ? 0 : scur + 1;
        snxt = (snxt == 2) ? 0 : snxt + 1;
    }

    // ---- Z reduce ----
#pragma unroll
    for (int ri = 0; ri < 4; ri++) {
        float z = zpart[ri];
#pragma unroll
        for (int o = 16; o; o >>= 1) z += __shfl_xor_sync(0xffffffffu, z, o);
        if (lane == 0) zs[w * 4 + ri] = z;
    }
    __syncthreads();

    // ---- epilogue ----
#pragma unroll
    for (int mt = 0; mt < 2; mt++) {
#pragma unroll
        for (int half = 0; half < 2; half++) {
            int rl = wm * 32 + mt * 16 + g + half * 8;
            float invz = 1.0f / zs[rl];
            float* orow = out + (size_t)(r0 + rl) * Ff + wn * 32 + 2 * t4;
#pragma unroll
            for (int s = 0; s < 4; s++) {
                float v0 = acc[mt][s][2 * half] * invz;
                float v1 = acc[mt][s][2 * half + 1] * invz;
                float2 o;
                o.x = (v0 > 0.f) ? v0 : expm1f(v0);
                o.y = (v1 > 0.f) ? v1 : expm1f(v1);
                *(float2*)(orow + s * 8) = o;
            }
        }
    }
}

// ================= launcher =================
extern "C" void kernel_launch(void* const* d_in, const int* in_sizes, int n_in,
                              void* d_out, int out_size) {
    const float* input = (const float*)d_in[0];
    const int*   adj   = (const int*)d_in[1];
    const float* W     = (const float*)d_in[2];
    const float* a     = (const float*)d_in[3];
    float* out = (float*)d_out;

    static int smem_set = 0;
    if (!smem_set) {
        cudaFuncSetAttribute(attn_main_kernel,
                             cudaFuncAttributeMaxDynamicSharedMemorySize, SMEM_MAIN);
        smem_set = 1;
    }

    dim3 g1(Ff / 64, Nn / 64);
    gemm_h_kernel<<<g1, 256>>>(input, W);
    attn_vec_kernel<<<Nn / 8, 256>>>(a);
    attn_main_kernel<<<Nn / BM, 512, SMEM_MAIN>>>(adj, out);
}

// round 15
// speedup vs baseline: 1.3019x; 1.2095x over previous
#include <cuda_runtime.h>
#include <cuda_fp16.h>
#include <cstdint>

#define Nn 8192
#define KIN 512
#define Ff 256
#define ALPHA 0.2f

#define BM 64
#define KC 64
#define NT (Nn / KC)      // 128
#define PSTR 40           // u32 row stride for P and B smem tiles (conflict-free)

// ---------------- scratch ----------------
__device__ float g_h[Nn * Ff];
__device__ uint32_t g_ht[Ff * Nn / 2];  // h^T fp16 pairs, pair-permuted in 8-pair groups
__device__ float g_sself[Nn];
__device__ float g_e1[Nn];
__device__ float g_e2[Nn];
__device__ float g_sneigh[Nn];
__device__ unsigned g_smax_bits;

// ---------------- helpers ----------------
__device__ __forceinline__ void mma_f16(float* d, uint32_t a0, uint32_t a1,
                                        uint32_t a2, uint32_t a3,
                                        uint32_t b0, uint32_t b1) {
    asm volatile(
        "mma.sync.aligned.m16n8k16.row.col.f32.f16.f16.f32 "
        "{%0,%1,%2,%3}, {%4,%5,%6,%7}, {%8,%9}, {%0,%1,%2,%3};"
        : "+f"(d[0]), "+f"(d[1]), "+f"(d[2]), "+f"(d[3])
        : "r"(a0), "r"(a1), "r"(a2), "r"(a3), "r"(b0), "r"(b1));
}
__device__ __forceinline__ unsigned fkey(float f) {
    unsigned b = __float_as_uint(f);
    return (b & 0x80000000u) ? ~b : (b | 0x80000000u);
}
__device__ __forceinline__ float funkey(unsigned k) {
    unsigned b = (k & 0x80000000u) ? (k & 0x7fffffffu) : ~k;
    return __uint_as_float(b);
}
__device__ __forceinline__ uint32_t smem_u32(const void* p) {
    uint32_t a;
    asm("{ .reg .u64 t; cvta.to.shared.u64 t, %1; cvt.u32.u64 %0, t; }"
        : "=r"(a) : "l"(p));
    return a;
}
__device__ __forceinline__ void cp16(uint32_t dst, const void* src) {
    asm volatile("cp.async.cg.shared.global [%0], [%1], 16;"
                 :: "r"(dst), "l"(src));
}

// ================= kernel 1: h = X @ W =================
__global__ __launch_bounds__(256, 1) void gemm_h_kernel(
    const float* __restrict__ A, const float* __restrict__ B) {
    __shared__ float As[32][65];
    __shared__ float Bs[32][64];
    int tid = threadIdx.x;
    if (blockIdx.x == 0 && blockIdx.y == 0 && tid == 0) g_smax_bits = 0u;
    int tx = tid & 15, ty = tid >> 4;
    int m0 = blockIdx.y * 64, n0 = blockIdx.x * 64;
    float acc[4][4];
#pragma unroll
    for (int i = 0; i < 4; i++)
#pragma unroll
        for (int j = 0; j < 4; j++) acc[i][j] = 0.f;
    for (int k0 = 0; k0 < KIN; k0 += 32) {
#pragma unroll
        for (int v = 0; v < 8; v++) {
            int idx = v * 256 + tid;
            int m = idx >> 5, k = idx & 31;
            As[k][m] = A[(size_t)(m0 + m) * KIN + k0 + k];
        }
#pragma unroll
        for (int v = 0; v < 8; v++) {
            int idx = v * 256 + tid;
            int k = idx >> 6, n = idx & 63;
            Bs[k][n] = B[(size_t)(k0 + k) * Ff + n0 + n];
        }
        __syncthreads();
#pragma unroll
        for (int k = 0; k < 32; k++) {
            float a0[4], b0[4];
#pragma unroll
            for (int i = 0; i < 4; i++) a0[i] = As[k][ty * 4 + i];
            float4 bv = *(const float4*)&Bs[k][tx * 4];
            b0[0] = bv.x; b0[1] = bv.y; b0[2] = bv.z; b0[3] = bv.w;
#pragma unroll
            for (int i = 0; i < 4; i++)
#pragma unroll
                for (int j = 0; j < 4; j++) acc[i][j] += a0[i] * b0[j];
        }
        __syncthreads();
    }
#pragma unroll
    for (int i = 0; i < 4; i++) {
        float4 o = make_float4(acc[i][0], acc[i][1], acc[i][2], acc[i][3]);
        *(float4*)&g_h[(size_t)(m0 + ty * 4 + i) * Ff + n0 + tx * 4] = o;
    }
}

// ================= kernel 1b: transpose + fp16 convert (pair-permuted) =================
// pair p (j=2p,2p+1) within an 8-pair group lands at slot 2*(p&3)+(p>>2)
__global__ __launch_bounds__(256) void transpose_f16_kernel() {
    __shared__ float ts[64][65];
    int m0 = blockIdx.x * 64;   // j
    int n0 = blockIdx.y * 64;   // f
    int tid = threadIdx.x;
    int c = tid & 63, r = tid >> 6;
#pragma unroll
    for (int rr = 0; rr < 16; rr++)
        ts[r + rr * 4][c] = g_h[(size_t)(m0 + r + rr * 4) * Ff + n0 + c];
    __syncthreads();
    int nl = tid >> 2;          // f local
    int mb = (tid & 3) * 16;    // 16 j = one 8-pair group
    uint32_t* dst = g_ht + (size_t)(n0 + nl) * (Nn / 2) + (m0 >> 1);
#pragma unroll
    for (int q = 0; q < 8; q++) {
        __half2 h = __floats2half2_rn(ts[mb + 2 * q][nl], ts[mb + 2 * q + 1][nl]);
        int slot = 2 * (q & 3) + (q >> 2);
        dst[(mb >> 1) + slot] = *(uint32_t*)&h;
    }
}

// ================= kernel 2: s_self / s_neigh + e1,e2 + global max (warp-per-row) =====
__global__ __launch_bounds__(256) void attn_vec_kernel(const float* __restrict__ a) {
    int w = threadIdx.x >> 5, lane = threadIdx.x & 31;
    int i = blockIdx.x * 8 + w;
    const float4* hrow = (const float4*)(g_h + (size_t)i * Ff);
    float p1 = 0.f, p2 = 0.f;
#pragma unroll
    for (int q = 0; q < 2; q++) {
        int e = lane + q * 32;
        float4 v = hrow[e];
        float4 a1 = *(const float4*)(a + 4 * e);
        float4 a2 = *(const float4*)(a + Ff + 4 * e);
        p1 += v.x * a1.x + v.y * a1.y + v.z * a1.z + v.w * a1.w;
        p2 += v.x * a2.x + v.y * a2.y + v.z * a2.z + v.w * a2.w;
    }
#pragma unroll
    for (int o = 16; o; o >>= 1) {
        p1 += __shfl_down_sync(0xffffffffu, p1, o);
        p2 += __shfl_down_sync(0xffffffffu, p2, o);
    }
    if (lane == 0) {
        g_sself[i] = p1;
        g_sneigh[i] = p2;
        g_e1[i] = __expf(p2);
        g_e2[i] = __expf(ALPHA * p2);
        atomicMax(&g_smax_bits, fkey(p2));
    }
}

// ================= kernel 3: fp16 HMMA masked softmax-GEMM (round-11 + adj L2 prefetch) =
// 512 threads. Warp (wm,wn): rows wm*32+, cols wn*32+. P-gen: warp w rows w*4..w*4+3.
#define SMEM_MAIN ((2 * 256 * PSTR + 2 * BM * PSTR) * 4 + BM * 4)
__global__ __launch_bounds__(512, 1) void attn_main_kernel(
    const int* __restrict__ adj, float* __restrict__ out) {
    extern __shared__ char smem[];
    uint32_t* bs = (uint32_t*)smem;                  // [2][256][PSTR]
    uint32_t* ps = bs + 2 * 256 * PSTR;              // [2][BM][PSTR]
    float* zs = (float*)(ps + 2 * BM * PSTR);        // [BM]

    int tid = threadIdx.x, w = tid >> 5, lane = tid & 31;
    int g = lane >> 2, t4 = lane & 3;
    int r0 = blockIdx.x * BM;

    // ---- per-thread row constants (4 rows per warp) ----
    float c1r[4], c2r[4], thrr[4];
    float smax = funkey(g_smax_bits);
#pragma unroll
    for (int ri = 0; ri < 4; ri++) {
        float ss = g_sself[r0 + w * 4 + ri];
        float x = ss + smax;
        float m = (x >= 0.f) ? x : ALPHA * x;
        c1r[ri] = __expf(ss - m);
        c2r[ri] = __expf(ALPHA * ss - m);
        thrr[ri] = -ss;
    }

    // P-gen: thread owns j-pair = lane (j = 2*lane, 2*lane+1)
    int j0 = 2 * lane;
    int l7 = lane & 7;
    int pcol = ((lane >> 3) << 3) + 2 * (l7 & 3) + (l7 >> 2);

    // cp.async B: thread owns f-row tid>>1, quarter-row (tid&1)*16 u32
    int brow = tid >> 1, bq = (tid & 1) * 16;
    const uint32_t* srcB = g_ht + (size_t)brow * (Nn / 2) + bq;
    uint32_t sb = smem_u32(smem);
    uint32_t dstB[2] = {sb + (uint32_t)(brow * PSTR + bq) * 4,
                        sb + (uint32_t)(256 * PSTR + brow * PSTR + bq) * 4};

    // ---- prologue: issue B0 and B1 ----
#pragma unroll
    for (int b = 0; b < 4; b++)
        cp16(dstB[0] + b * 16, srcB + b * 4);
    asm volatile("cp.async.commit_group;");
#pragma unroll
    for (int b = 0; b < 4; b++)
        cp16(dstB[1] + b * 16, srcB + (KC / 2) + b * 4);
    asm volatile("cp.async.commit_group;");

    // ---- state chunk 0; gen P0 ----
    const int* abase = adj + (size_t)(r0 + w * 4) * Nn;
    int2 av[4];
    float2 e1v, e2v, snv;
#pragma unroll
    for (int ri = 0; ri < 4; ri++) av[ri] = *(const int2*)(abase + (size_t)ri * Nn + j0);
    e1v = *(const float2*)&g_e1[j0];
    e2v = *(const float2*)&g_e2[j0];
    snv = *(const float2*)&g_sneigh[j0];

    float zpart[4];
#pragma unroll
    for (int ri = 0; ri < 4; ri++) zpart[ri] = 0.f;

    {
        uint32_t* pw = ps + (w * 4) * PSTR;
#pragma unroll
        for (int ri = 0; ri < 4; ri++) {
            int2 a = av[ri];
            bool pos0 = snv.x >= thrr[ri];
            float p0 = (pos0 ? c1r[ri] : c2r[ri]) * (pos0 ? e1v.x : e2v.x);
            p0 = (a.x > 0) ? p0 : 0.f;
            bool pos1 = snv.y >= thrr[ri];
            float p1 = (pos1 ? c1r[ri] : c2r[ri]) * (pos1 ? e1v.y : e2v.y);
            p1 = (a.y > 0) ? p1 : 0.f;
            zpart[ri] += p0 + p1;
            __half2 h = __floats2half2_rn(p0, p1);
            pw[ri * PSTR + pcol] = *(uint32_t*)&h;
        }
    }

    // state chunk 1
#pragma unroll
    for (int ri = 0; ri < 4; ri++)
        av[ri] = *(const int2*)(abase + (size_t)ri * Nn + KC + j0);
    e1v = *(const float2*)&g_e1[KC + j0];
    e2v = *(const float2*)&g_e2[KC + j0];
    snv = *(const float2*)&g_sneigh[KC + j0];

    asm volatile("cp.async.wait_group 1;");   // B0 resident
    __syncthreads();

    int wm = w & 1, wn = w >> 1;
    float acc[2][4][4];
#pragma unroll
    for (int mt = 0; mt < 2; mt++)
#pragma unroll
        for (int s = 0; s < 4; s++)
#pragma unroll
            for (int q = 0; q < 4; q++) acc[mt][s][q] = 0.f;

    for (int tch = 0; tch < NT; tch++) {
        int buf = tch & 1;

        // ---- genP(t+1) into ps[buf^1] ----
        if (tch + 1 < NT) {
            uint32_t* pw = ps + (buf ^ 1) * BM * PSTR + (w * 4) * PSTR;
#pragma unroll
            for (int ri = 0; ri < 4; ri++) {
                int2 a = av[ri];
                bool pos0 = snv.x >= thrr[ri];
                float p0 = (pos0 ? c1r[ri] : c2r[ri]) * (pos0 ? e1v.x : e2v.x);
                p0 = (a.x > 0) ? p0 : 0.f;
                bool pos1 = snv.y >= thrr[ri];
                float p1 = (pos1 ? c1r[ri] : c2r[ri]) * (pos1 ? e1v.y : e2v.y);
                p1 = (a.y > 0) ? p1 : 0.f;
                zpart[ri] += p0 + p1;
                __half2 h = __floats2half2_rn(p0, p1);
                pw[ri * PSTR + pcol] = *(uint32_t*)&h;
            }
        }

        // ---- L2 prefetch of adj for chunk t+3 (covers DRAM latency; no registers held) ----
        if (tch + 3 < NT) {
            const int* pf = abase + (size_t)(tch + 3) * KC + j0;
#pragma unroll
            for (int ri = 0; ri < 4; ri++)
                asm volatile("prefetch.global.L2 [%0];" :: "l"(pf + (size_t)ri * Nn));
        }

        // ---- MMA(t): warp tile 32x32, K=64 (4 k-steps of 16) ----
        {
            const uint32_t* bt = bs + buf * 256 * PSTR + (wn * 32 + g) * PSTR + 2 * t4;
            const uint32_t* pa = ps + buf * BM * PSTR + (wm * 32) * PSTR + 2 * t4;
#pragma unroll
            for (int kk = 0; kk < 4; kk++) {
                int co = kk * 8;
                uint2 ra0 = *(const uint2*)(pa + (g) * PSTR + co);
                uint2 ra1 = *(const uint2*)(pa + (g + 8) * PSTR + co);
                uint2 ra2 = *(const uint2*)(pa + (16 + g) * PSTR + co);
                uint2 ra3 = *(const uint2*)(pa + (16 + g + 8) * PSTR + co);
#pragma unroll
                for (int s = 0; s < 4; s++) {
                    uint2 b = *(const uint2*)(bt + (s * 8) * PSTR + co);
                    mma_f16(acc[0][s], ra0.x, ra1.x, ra0.y, ra1.y, b.x, b.y);
                    mma_f16(acc[1][s], ra2.x, ra3.x, ra2.y, ra3.y, b.x, b.y);
                }
            }
        }

        // ---- prefetch state(t+2) (adj now L2-hot from the prefetch 3 chunks ago) ----
        if (tch + 2 < NT) {
            int jn = (tch + 2) * KC + j0;
#pragma unroll
            for (int ri = 0; ri < 4; ri++)
                av[ri] = *(const int2*)(abase + (size_t)ri * Nn + jn);
            e1v = *(const float2*)&g_e1[jn];
            e2v = *(const float2*)&g_e2[jn];
            snv = *(const float2*)&g_sneigh[jn];
        }

        asm volatile("cp.async.wait_group 0;");   // B(t+1) resident
        __syncthreads();                          // ps[buf^1] + bs[buf] free

        // ---- issue B(t+2) into bs[buf] ----
        if (tch + 2 < NT) {
            const uint32_t* s = srcB + (size_t)(tch + 2) * (KC / 2);
#pragma unroll
            for (int b = 0; b < 4; b++)
                cp16(dstB[buf] + b * 16, s + b * 4);
        }
        asm volatile("cp.async.commit_group;");
    }

    // ---- Z reduce ----
#pragma unroll
    for (int ri = 0; ri < 4; ri++) {
        float z = zpart[ri];
#pragma unroll
        for (int o = 16; o; o >>= 1) z += __shfl_xor_sync(0xffffffffu, z, o);
        if (lane == 0) zs[w * 4 + ri] = z;
    }
    __syncthreads();

    // ---- epilogue ----
#pragma unroll
    for (int mt = 0; mt < 2; mt++) {
#pragma unroll
        for (int half = 0; half < 2; half++) {
            int rl = wm * 32 + mt * 16 + g + half * 8;
            float invz = 1.0f / zs[rl];
            float* orow = out + (size_t)(r0 + rl) * Ff + wn * 32 + 2 * t4;
#pragma unroll
            for (int s = 0; s < 4; s++) {
                float v0 = acc[mt][s][2 * half] * invz;
                float v1 = acc[mt][s][2 * half + 1] * invz;
                float2 o;
                o.x = (v0 > 0.f) ? v0 : expm1f(v0);
                o.y = (v1 > 0.f) ? v1 : expm1f(v1);
                *(float2*)(orow + s * 8) = o;
            }
        }
    }
}

// ================= launcher =================
extern "C" void kernel_launch(void* const* d_in, const int* in_sizes, int n_in,
                              void* d_out, int out_size) {
    const float* input = (const float*)d_in[0];
    const int*   adj   = (const int*)d_in[1];
    const float* W     = (const float*)d_in[2];
    const float* a     = (const float*)d_in[3];
    float* out = (float*)d_out;

    static int smem_set = 0;
    if (!smem_set) {
        cudaFuncSetAttribute(attn_main_kernel,
                             cudaFuncAttributeMaxDynamicSharedMemorySize, SMEM_MAIN);
        smem_set = 1;
    }

    dim3 g1(Ff / 64, Nn / 64);
    gemm_h_kernel<<<g1, 256>>>(input, W);
    dim3 g2(Nn / 64, Ff / 64);
    transpose_f16_kernel<<<g2, 256>>>();
    attn_vec_kernel<<<Nn / 8, 256>>>(a);
    attn_main_kernel<<<Nn / BM, 512, SMEM_MAIN>>>(adj, out);
}